// round 2
// baseline (speedup 1.0000x reference)
#include <cuda_runtime.h>
#include <cuda_bf16.h>
#include <cstdint>

// Problem constants (from reference_code)
constexpr int NNB     = 16;        // N_NEIGH
constexpr int NFEAT   = 32;        // N_FEAT
constexpr int ROW     = 3 + 3 * NFEAT;   // 99 features per pair
constexpr int PAIRS   = NNB * NNB - NNB; // 240 off-diagonal pairs
constexpr int PER_C   = PAIRS * ROW;     // 23760 floats per center

__global__ void __launch_bounds__(256)
ang_desc_kernel(const float* __restrict__ atoms_xyz,   // [N_ATOMS,3]
                const float* __restrict__ embed,       // [N_TYPES,32]
                const float* __restrict__ dist,        // [C,16]
                const int*   __restrict__ types,       // [N_ATOMS]
                const int*   __restrict__ i_idx,       // [C]
                const int*   __restrict__ j_idx,       // [C,16]
                float*       __restrict__ out,         // [C,240,99]
                float*       __restrict__ centers_out) // [C]
{
    const int c = blockIdx.x;
    const int t = threadIdx.x;

    __shared__ float s_d[NNB];            // dist row
    __shared__ float s_inv[NNB];          // 1/dist
    __shared__ float s_embi[NFEAT];       // center embedding
    __shared__ float s_embj[NNB * NFEAT]; // neighbor embeddings pre-scaled by 1/d
    __shared__ float s_norm[NNB * NNB];   // d_jk_norm, indexed q = j*16+k
    __shared__ float s_x[NNB], s_y[NNB], s_z[NNB];
    __shared__ int   s_aj[NNB];
    __shared__ int   s_tj[NNB];
    __shared__ int   s_ti;

    // ---- Phase A: independent global loads ----
    if (t < NNB) {
        float d = dist[c * NNB + t];
        s_d[t]   = d;
        s_inv[t] = 1.0f / d;
        s_aj[t]  = j_idx[c * NNB + t];
    } else if (t == NNB) {
        int ai = i_idx[c];
        s_ti = types[ai];
        centers_out[c] = (float)ai;
    }
    __syncthreads();

    // ---- Phase B: dependent gathers ----
    if (t < NNB) {
        int a = s_aj[t];
        s_x[t] = atoms_xyz[a * 3 + 0];
        s_y[t] = atoms_xyz[a * 3 + 1];
        s_z[t] = atoms_xyz[a * 3 + 2];
        s_tj[t] = types[a];
    } else if (t >= 32 && t < 64) {
        s_embi[t - 32] = embed[s_ti * NFEAT + (t - 32)];
    }
    __syncthreads();

    // ---- Phase C: scaled neighbor-embedding table + d_jk_norm table ----
    for (int idx = t; idx < NNB * NFEAT; idx += 256) {
        int nb = idx >> 5;
        int f  = idx & 31;
        s_embj[idx] = embed[s_tj[nb] * NFEAT + f] * s_inv[nb];
    }
    {
        int j = t >> 4, k = t & 15;
        float dx = s_x[j] - s_x[k];
        float dy = s_y[j] - s_y[k];
        float dz = s_z[j] - s_z[k];
        float djk = sqrtf(dx * dx + dy * dy + dz * dz);
        float dj = s_d[j], dk = s_d[k];
        float mx = fmaxf(dj, dk), mn = fminf(dj, dk);
        s_norm[t] = (djk - mx + mn) / (2.0f * mn);
    }
    __syncthreads();

    // ---- Phase D: warp-per-j-row streaming writes ----
    // Lane rotation (lane-3)&31 bakes the f-offset of the ej/ek blocks into a
    // single conflict-free shared load per (row|pair); one register then serves
    // both the lane>=3 body and the lane<3 tail of the next pass.
    const int warp = t >> 5;
    const int lane = t & 31;
    const int rot  = (lane - 3) & 31;

    const float embi_a = s_embi[rot];                                  // lanes>=3, pass0
    const float embi_b = s_embi[(29 + lane) < NFEAT ? (29 + lane) : 0]; // lanes<3, pass1
    const bool  l0 = (lane == 0), l1 = (lane == 1), l2 = (lane == 2);
    const bool  llt3 = (lane < 3);

    float* base = out + (size_t)c * PER_C;

    for (int j = warp; j < NNB; j += 8) {
        const float ejv = s_embj[j * NFEAT + rot];   // serves pass1(lane>=3) & pass2(lane<3)
        const float dj  = s_d[j];
        float* rb = base + (j * (NNB - 1)) * ROW;

        #pragma unroll
        for (int k = 0; k < NNB; ++k) {
            if (k == j) continue;                    // warp-uniform, no divergence
            const float ekv = s_embj[k * NFEAT + rot]; // serves pass2(lane>=3) & pass3(lane<3)
            const float dk  = s_d[k];
            const float njk = s_norm[j * NNB + k];

            float v0 = embi_a;                       // pass0: [dj, dk, njk, emb_i[0..28]]
            if (l2) v0 = njk;
            if (l1) v0 = dk;
            if (l0) v0 = dj;
            float v1 = llt3 ? embi_b : ejv;          // pass1: [emb_i[29..31], e_j[0..28]]
            float v2 = llt3 ? ejv    : ekv;          // pass2: [e_j[29..31],  e_k[0..28]]

            rb[lane]      = v0;
            rb[32 + lane] = v1;
            rb[64 + lane] = v2;
            if (llt3) rb[96 + lane] = ekv;           // pass3: e_k[29..31]

            rb += ROW;
        }
    }
}

extern "C" void kernel_launch(void* const* d_in, const int* in_sizes, int n_in,
                              void* d_out, int out_size)
{
    const float* atoms_xyz = (const float*)d_in[0];
    const float* embed     = (const float*)d_in[1];
    const float* dist      = (const float*)d_in[2];
    const int*   types     = (const int*)  d_in[3];
    const int*   i_idx     = (const int*)  d_in[4];
    const int*   j_idx     = (const int*)  d_in[5];

    const int C = in_sizes[4];                 // number of centers
    float* out = (float*)d_out;
    float* centers_out = out + (size_t)C * PER_C;

    ang_desc_kernel<<<C, 256>>>(atoms_xyz, embed, dist, types,
                                i_idx, j_idx, out, centers_out);
}

// round 3
// speedup vs baseline: 1.0243x; 1.0243x over previous
#include <cuda_runtime.h>
#include <cuda_bf16.h>
#include <cstdint>

// Problem constants (from reference_code)
constexpr int NNB     = 16;        // N_NEIGH
constexpr int NFEAT   = 32;        // N_FEAT
constexpr int ROW     = 3 + 3 * NFEAT;   // 99 features per pair
constexpr int PAIRS   = NNB * NNB - NNB; // 240 off-diagonal pairs
constexpr int PER_C   = PAIRS * ROW;     // 23760 floats per center

__global__ void __launch_bounds__(256)
ang_desc_kernel(const float* __restrict__ atoms_xyz,   // [N_ATOMS,3]
                const float* __restrict__ embed,       // [N_TYPES,32]
                const float* __restrict__ dist,        // [C,16]
                const int*   __restrict__ types,       // [N_ATOMS]
                const int*   __restrict__ i_idx,       // [C]
                const int*   __restrict__ j_idx,       // [C,16]
                float*       __restrict__ out,         // [C,240,99]
                float*       __restrict__ centers_out) // [C]
{
    const int c = blockIdx.x;
    const int t = threadIdx.x;

    __shared__ float s_d[NNB];            // dist row
    __shared__ float s_inv[NNB];          // 1/dist
    __shared__ float s_embi[NFEAT];       // center embedding
    __shared__ float s_embj[NNB * NFEAT]; // neighbor embeddings pre-scaled by 1/d
    __shared__ float s_norm[NNB * NNB];   // d_jk_norm, indexed q = j*16+k
    __shared__ float s_x[NNB], s_y[NNB], s_z[NNB];
    __shared__ int   s_tj[NNB];

    // ---- Phase A+B fused: register-chained gathers, ONE sync ----
    if (t < NNB) {
        // warp 0: per-neighbor chain j_idx -> (atoms_xyz, types), no smem hop
        float d = dist[c * NNB + t];
        int   a = j_idx[c * NNB + t];
        s_d[t]   = d;
        s_inv[t] = 1.0f / d;
        s_x[t]  = atoms_xyz[a * 3 + 0];
        s_y[t]  = atoms_xyz[a * 3 + 1];
        s_z[t]  = atoms_xyz[a * 3 + 2];
        s_tj[t] = types[a];
    } else if (t >= 32 && t < 64) {
        // warp 1: center chain i_idx -> types -> embed (all-lane broadcast loads)
        int lane = t - 32;
        int ai = i_idx[c];            // same addr all lanes -> broadcast
        int ti = types[ai];           // same addr all lanes -> broadcast
        s_embi[lane] = embed[ti * NFEAT + lane];
        if (lane == 0) centers_out[c] = (float)ai;
    }
    __syncthreads();

    // ---- Phase C: scaled neighbor-embedding table + d_jk_norm table ----
    for (int idx = t; idx < NNB * NFEAT; idx += 256) {
        int nb = idx >> 5;
        int f  = idx & 31;
        s_embj[idx] = embed[s_tj[nb] * NFEAT + f] * s_inv[nb];
    }
    {
        int j = t >> 4, k = t & 15;
        float dx = s_x[j] - s_x[k];
        float dy = s_y[j] - s_y[k];
        float dz = s_z[j] - s_z[k];
        float djk = sqrtf(dx * dx + dy * dy + dz * dz);
        float dj = s_d[j], dk = s_d[k];
        float mx = fmaxf(dj, dk), mn = fminf(dj, dk);
        s_norm[t] = (djk - mx + mn) / (2.0f * mn);
    }
    __syncthreads();

    // ---- Phase D: interleaved warp-per-row streaming writes (R1 order:
    // the 8 warps write 8 temporally-adjacent rows -> tight DRAM page window) ----
    const int warp = t >> 5;
    const int lane = t & 31;
    const int rot  = (lane - 3) & 31;

    const float embi_a = s_embi[rot];                                   // lanes>=3, pass0
    const float embi_b = s_embi[(29 + lane) < NFEAT ? (29 + lane) : 0]; // lanes<3, pass1
    const bool  l0 = (lane == 0), l1 = (lane == 1), l2 = (lane == 2);
    const bool  llt3 = (lane < 3);

    float* base = out + (size_t)c * PER_C;

    #pragma unroll 2
    for (int p = warp; p < PAIRS; p += 8) {
        int q = p + (p >> 4) + 1;     // flat n*n index skipping the diagonal
        int j = q >> 4;
        int k = q & 15;

        const float dj  = s_d[j];
        const float dk  = s_d[k];
        const float njk = s_norm[q];
        const float ejv = s_embj[j * NFEAT + rot]; // serves pass1(lane>=3) & pass2(lane<3)
        const float ekv = s_embj[k * NFEAT + rot]; // serves pass2(lane>=3) & pass3(lane<3)

        float v0 = embi_a;                         // pass0: [dj, dk, njk, emb_i[0..28]]
        if (l2) v0 = njk;
        if (l1) v0 = dk;
        if (l0) v0 = dj;
        float v1 = llt3 ? embi_b : ejv;            // pass1: [emb_i[29..31], e_j[0..28]]
        float v2 = llt3 ? ejv    : ekv;            // pass2: [e_j[29..31],  e_k[0..28]]

        float* rb = base + p * ROW;
        rb[lane]      = v0;
        rb[32 + lane] = v1;
        rb[64 + lane] = v2;
        if (llt3) rb[96 + lane] = ekv;             // pass3: e_k[29..31]
    }
}

extern "C" void kernel_launch(void* const* d_in, const int* in_sizes, int n_in,
                              void* d_out, int out_size)
{
    const float* atoms_xyz = (const float*)d_in[0];
    const float* embed     = (const float*)d_in[1];
    const float* dist      = (const float*)d_in[2];
    const int*   types     = (const int*)  d_in[3];
    const int*   i_idx     = (const int*)  d_in[4];
    const int*   j_idx     = (const int*)  d_in[5];

    const int C = in_sizes[4];                 // number of centers
    float* out = (float*)d_out;
    float* centers_out = out + (size_t)C * PER_C;

    ang_desc_kernel<<<C, 256>>>(atoms_xyz, embed, dist, types,
                                i_idx, j_idx, out, centers_out);
}

// round 4
// speedup vs baseline: 1.0337x; 1.0092x over previous
#include <cuda_runtime.h>
#include <cuda_bf16.h>
#include <cstdint>

// Problem constants (from reference_code)
constexpr int NNB     = 16;        // N_NEIGH
constexpr int NFEAT   = 32;        // N_FEAT
constexpr int ROW     = 3 + 3 * NFEAT;   // 99 features per pair
constexpr int PAIRS   = NNB * NNB - NNB; // 240 off-diagonal pairs
constexpr int PER_C   = PAIRS * ROW;     // 23760 floats per center
constexpr int GP      = 4;               // pairs per bulk group (4*396B = 1584B, 16B-mult)
constexpr int NGROUPS = PAIRS / GP;      // 60 groups per center
constexpr int GBYTES  = GP * ROW * 4;    // 1584

__global__ void __launch_bounds__(256)
ang_desc_kernel(const float* __restrict__ atoms_xyz,   // [N_ATOMS,3]
                const float* __restrict__ embed,       // [N_TYPES,32]
                const float* __restrict__ dist,        // [C,16]
                const int*   __restrict__ types,       // [N_ATOMS]
                const int*   __restrict__ i_idx,       // [C]
                const int*   __restrict__ j_idx,       // [C,16]
                float*       __restrict__ out,         // [C,240,99]
                float*       __restrict__ centers_out) // [C]
{
    const int c = blockIdx.x;
    const int t = threadIdx.x;

    __shared__ float s_d[NNB];
    __shared__ float s_inv[NNB];
    __shared__ float s_embi[NFEAT];
    __shared__ float s_embj[NNB * NFEAT]; // neighbor embeddings pre-scaled by 1/d
    __shared__ float s_norm[NNB * NNB];   // d_jk_norm, indexed q = j*16+k
    __shared__ float s_x[NNB], s_y[NNB], s_z[NNB];
    __shared__ int   s_tj[NNB];
    // per-warp double-buffered staging: [warp][stage][4 pairs * 99 floats]
    __shared__ __align__(16) float s_stage[8][2][GP * ROW];

    // ---- Phase A+B fused: register-chained gathers, one sync ----
    if (t < NNB) {
        float d = dist[c * NNB + t];
        int   a = j_idx[c * NNB + t];
        s_d[t]   = d;
        s_inv[t] = 1.0f / d;
        s_x[t]  = atoms_xyz[a * 3 + 0];
        s_y[t]  = atoms_xyz[a * 3 + 1];
        s_z[t]  = atoms_xyz[a * 3 + 2];
        s_tj[t] = types[a];
    } else if (t >= 32 && t < 64) {
        int lane = t - 32;
        int ai = i_idx[c];            // broadcast
        int ti = types[ai];           // broadcast
        s_embi[lane] = embed[ti * NFEAT + lane];
        if (lane == 0) centers_out[c] = (float)ai;
    }
    __syncthreads();

    // ---- Phase C: scaled neighbor-embedding table + d_jk_norm table ----
    for (int idx = t; idx < NNB * NFEAT; idx += 256) {
        int nb = idx >> 5;
        int f  = idx & 31;
        s_embj[idx] = embed[s_tj[nb] * NFEAT + f] * s_inv[nb];
    }
    {
        int j = t >> 4, k = t & 15;
        float dx = s_x[j] - s_x[k];
        float dy = s_y[j] - s_y[k];
        float dz = s_z[j] - s_z[k];
        float djk = sqrtf(dx * dx + dy * dy + dz * dz);
        float dj = s_d[j], dk = s_d[k];
        float mx = fmaxf(dj, dk), mn = fminf(dj, dk);
        s_norm[t] = (djk - mx + mn) / (2.0f * mn);
    }
    __syncthreads();

    // ---- Phase D: build rows in SMEM, drain via cp.async.bulk (L1-bypass,
    // fully sequential full-sector DRAM bursts) ----
    const int warp = t >> 5;
    const int lane = t & 31;
    const int rot  = (lane - 3) & 31;

    const float embi_a = s_embi[rot];
    const float embi_b = s_embi[(29 + lane) < NFEAT ? (29 + lane) : 0];
    const bool  l0 = (lane == 0), l1 = (lane == 1), l2 = (lane == 2);
    const bool  llt3 = (lane < 3);

    char* gbase = (char*)(out + (size_t)c * PER_C);

    int it = 0;
    for (int g = warp; g < NGROUPS; g += 8, ++it) {
        const int s = it & 1;
        if (it >= 2) {
            // oldest of the two in-flight groups must be done before buffer reuse
            if (lane == 0)
                asm volatile("cp.async.bulk.wait_group 1;" ::: "memory");
            __syncwarp();
        }

        float* buf = &s_stage[warp][s][0];
        const int p0 = g * GP;

        #pragma unroll
        for (int r = 0; r < GP; ++r) {
            const int p = p0 + r;
            const int q = p + (p >> 4) + 1;  // flat n*n index skipping diagonal
            const int j = q >> 4;
            const int k = q & 15;

            const float dj  = s_d[j];
            const float dk  = s_d[k];
            const float njk = s_norm[q];
            const float ejv = s_embj[j * NFEAT + rot];
            const float ekv = s_embj[k * NFEAT + rot];

            float v0 = embi_a;               // [dj, dk, njk, emb_i[0..28]]
            if (l2) v0 = njk;
            if (l1) v0 = dk;
            if (l0) v0 = dj;
            float v1 = llt3 ? embi_b : ejv;  // [emb_i[29..31], e_j[0..28]]
            float v2 = llt3 ? ejv    : ekv;  // [e_j[29..31],  e_k[0..28]]

            float* rb = buf + r * ROW;
            rb[lane]      = v0;
            rb[32 + lane] = v1;
            rb[64 + lane] = v2;
            if (llt3) rb[96 + lane] = ekv;   // e_k[29..31]
        }

        // order generic-proxy STS before async-proxy bulk read
        asm volatile("fence.proxy.async.shared::cta;" ::: "memory");
        __syncwarp();
        if (lane == 0) {
            uint32_t saddr = (uint32_t)__cvta_generic_to_shared(buf);
            asm volatile(
                "cp.async.bulk.global.shared::cta.bulk_group [%0], [%1], %2;"
                :: "l"(gbase + (size_t)g * GBYTES), "r"(saddr), "n"(GBYTES)
                : "memory");
            asm volatile("cp.async.bulk.commit_group;" ::: "memory");
        }
    }
    // drain all outstanding bulk stores before exit
    if (lane == 0)
        asm volatile("cp.async.bulk.wait_group 0;" ::: "memory");
}

extern "C" void kernel_launch(void* const* d_in, const int* in_sizes, int n_in,
                              void* d_out, int out_size)
{
    const float* atoms_xyz = (const float*)d_in[0];
    const float* embed     = (const float*)d_in[1];
    const float* dist      = (const float*)d_in[2];
    const int*   types     = (const int*)  d_in[3];
    const int*   i_idx     = (const int*)  d_in[4];
    const int*   j_idx     = (const int*)  d_in[5];

    const int C = in_sizes[4];                 // number of centers
    float* out = (float*)d_out;
    float* centers_out = out + (size_t)C * PER_C;

    ang_desc_kernel<<<C, 256>>>(atoms_xyz, embed, dist, types,
                                i_idx, j_idx, out, centers_out);
}

// round 5
// speedup vs baseline: 1.0645x; 1.0298x over previous
#include <cuda_runtime.h>
#include <cuda_bf16.h>
#include <cstdint>

// Problem constants (from reference_code)
constexpr int NNB     = 16;        // N_NEIGH
constexpr int NFEAT   = 32;        // N_FEAT
constexpr int ROW     = 3 + 3 * NFEAT;   // 99 features per pair
constexpr int PAIRS   = NNB * NNB - NNB; // 240 off-diagonal pairs
constexpr int PER_C   = PAIRS * ROW;     // 23760 floats per center

// CTA-wide slab staging: 48 pairs per slab (8 warps x 6 pairs), 5 slabs/center
constexpr int SLAB_PAIRS = 48;
constexpr int NSLABS     = PAIRS / SLAB_PAIRS;      // 5
constexpr int SLAB_FLOATS = SLAB_PAIRS * ROW;       // 4752
constexpr int SLAB_BYTES  = SLAB_FLOATS * 4;        // 19008 (16B multiple)
constexpr int PPW        = SLAB_PAIRS / 8;          // 6 pairs per warp per slab

__global__ void __launch_bounds__(256)
ang_desc_kernel(const float* __restrict__ atoms_xyz,   // [N_ATOMS,3]
                const float* __restrict__ embed,       // [N_TYPES,32]
                const float* __restrict__ dist,        // [C,16]
                const int*   __restrict__ types,       // [N_ATOMS]
                const int*   __restrict__ i_idx,       // [C]
                const int*   __restrict__ j_idx,       // [C,16]
                float*       __restrict__ out,         // [C,240,99]
                float*       __restrict__ centers_out) // [C]
{
    const int c = blockIdx.x;
    const int t = threadIdx.x;

    __shared__ float s_d[NNB];
    __shared__ float s_inv[NNB];
    __shared__ float s_embi[NFEAT];
    __shared__ float s_embj[NNB * NFEAT]; // neighbor embeddings pre-scaled by 1/d
    __shared__ float s_norm[NNB * NNB];   // d_jk_norm, indexed q = j*16+k
    __shared__ float s_x[NNB], s_y[NNB], s_z[NNB];
    __shared__ int   s_tj[NNB];
    // double-buffered CTA-wide slab: 2 x 19008 B
    __shared__ __align__(16) float s_stage[2][SLAB_FLOATS];

    // ---- Phase A+B fused: register-chained gathers, one sync ----
    if (t < NNB) {
        float d = dist[c * NNB + t];
        int   a = j_idx[c * NNB + t];
        s_d[t]   = d;
        s_inv[t] = 1.0f / d;
        s_x[t]  = atoms_xyz[a * 3 + 0];
        s_y[t]  = atoms_xyz[a * 3 + 1];
        s_z[t]  = atoms_xyz[a * 3 + 2];
        s_tj[t] = types[a];
    } else if (t >= 32 && t < 64) {
        int lane = t - 32;
        int ai = i_idx[c];            // broadcast
        int ti = types[ai];           // broadcast
        s_embi[lane] = embed[ti * NFEAT + lane];
        if (lane == 0) centers_out[c] = (float)ai;
    }
    __syncthreads();

    // ---- Phase C: scaled neighbor-embedding table + d_jk_norm table ----
    for (int idx = t; idx < NNB * NFEAT; idx += 256) {
        int nb = idx >> 5;
        int f  = idx & 31;
        s_embj[idx] = embed[s_tj[nb] * NFEAT + f] * s_inv[nb];
    }
    {
        int j = t >> 4, k = t & 15;
        float dx = s_x[j] - s_x[k];
        float dy = s_y[j] - s_y[k];
        float dz = s_z[j] - s_z[k];
        float djk = sqrtf(dx * dx + dy * dy + dz * dz);
        float dj = s_d[j], dk = s_d[k];
        float mx = fmaxf(dj, dk), mn = fminf(dj, dk);
        s_norm[t] = (djk - mx + mn) / (2.0f * mn);
    }
    __syncthreads();

    // ---- Phase D: build 48-pair slabs in SMEM, drain each via ONE 19KB
    // cp.async.bulk (5 bulk packets per center, big sequential DRAM bursts) ----
    const int warp = t >> 5;
    const int lane = t & 31;
    const int rot  = (lane - 3) & 31;

    const float embi_a = s_embi[rot];
    const float embi_b = s_embi[(29 + lane) < NFEAT ? (29 + lane) : 0];
    const bool  l0 = (lane == 0), l1 = (lane == 1), l2 = (lane == 2);
    const bool  llt3 = (lane < 3);

    char* gbase = (char*)(out + (size_t)c * PER_C);

    for (int s = 0; s < NSLABS; ++s) {
        float* buf = s_stage[s & 1];

        #pragma unroll
        for (int r = 0; r < PPW; ++r) {
            const int rp = warp * PPW + r;       // row within slab
            const int p  = s * SLAB_PAIRS + rp;  // global pair index
            const int q  = p + (p >> 4) + 1;     // flat n*n index skipping diag
            const int j  = q >> 4;
            const int k  = q & 15;

            const float dj  = s_d[j];
            const float dk  = s_d[k];
            const float njk = s_norm[q];
            const float ejv = s_embj[j * NFEAT + rot];
            const float ekv = s_embj[k * NFEAT + rot];

            float v0 = embi_a;               // [dj, dk, njk, emb_i[0..28]]
            if (l2) v0 = njk;
            if (l1) v0 = dk;
            if (l0) v0 = dj;
            float v1 = llt3 ? embi_b : ejv;  // [emb_i[29..31], e_j[0..28]]
            float v2 = llt3 ? ejv    : ekv;  // [e_j[29..31],  e_k[0..28]]

            float* rb = buf + rp * ROW;
            rb[lane]      = v0;
            rb[32 + lane] = v1;
            rb[64 + lane] = v2;
            if (llt3) rb[96 + lane] = ekv;   // e_k[29..31]
        }

        __syncthreads();   // all warps finished building this slab
        if (t == 0) {
            asm volatile("fence.proxy.async.shared::cta;" ::: "memory");
            uint32_t saddr = (uint32_t)__cvta_generic_to_shared(buf);
            asm volatile(
                "cp.async.bulk.global.shared::cta.bulk_group [%0], [%1], %2;"
                :: "l"(gbase + (size_t)s * SLAB_BYTES), "r"(saddr), "n"(SLAB_BYTES)
                : "memory");
            asm volatile("cp.async.bulk.commit_group;" ::: "memory");
            // keep at most 1 slab in flight beyond the one just committed:
            // guarantees buffer (s+1)&1 (used by slab s-1) is drained
            asm volatile("cp.async.bulk.wait_group 1;" ::: "memory");
        }
        __syncthreads();   // release builders for next slab
    }
    if (t == 0)
        asm volatile("cp.async.bulk.wait_group 0;" ::: "memory");
}

extern "C" void kernel_launch(void* const* d_in, const int* in_sizes, int n_in,
                              void* d_out, int out_size)
{
    const float* atoms_xyz = (const float*)d_in[0];
    const float* embed     = (const float*)d_in[1];
    const float* dist      = (const float*)d_in[2];
    const int*   types     = (const int*)  d_in[3];
    const int*   i_idx     = (const int*)  d_in[4];
    const int*   j_idx     = (const int*)  d_in[5];

    const int C = in_sizes[4];                 // number of centers
    float* out = (float*)d_out;
    float* centers_out = out + (size_t)C * PER_C;

    ang_desc_kernel<<<C, 256>>>(atoms_xyz, embed, dist, types,
                                i_idx, j_idx, out, centers_out);
}

// round 6
// speedup vs baseline: 1.1839x; 1.1122x over previous
#include <cuda_runtime.h>
#include <cuda_bf16.h>
#include <cstdint>

// Problem constants (from reference_code)
constexpr int NNB     = 16;        // N_NEIGH
constexpr int NFEAT   = 32;        // N_FEAT
constexpr int ROW     = 3 + 3 * NFEAT;   // 99 features per pair
constexpr int PAIRS   = NNB * NNB - NNB; // 240 off-diagonal pairs
constexpr int PER_C   = PAIRS * ROW;     // 23760 floats per center

// CTA-wide slab staging: 80 pairs per slab (8 warps x 10 pairs), 3 slabs/center
constexpr int SLAB_PAIRS  = 80;
constexpr int NSLABS      = PAIRS / SLAB_PAIRS;     // 3
constexpr int SLAB_FLOATS = SLAB_PAIRS * ROW;       // 7920
constexpr int SLAB_BYTES  = SLAB_FLOATS * 4;        // 31680 (16B multiple)
constexpr int PPW         = SLAB_PAIRS / 8;         // 10 pairs per warp per slab

__global__ void __launch_bounds__(256)
ang_desc_kernel(const float* __restrict__ atoms_xyz,   // [N_ATOMS,3]
                const float* __restrict__ embed,       // [N_TYPES,32]
                const float* __restrict__ dist,        // [C,16]
                const int*   __restrict__ types,       // [N_ATOMS]
                const int*   __restrict__ i_idx,       // [C]
                const int*   __restrict__ j_idx,       // [C,16]
                float*       __restrict__ out,         // [C,240,99]
                float*       __restrict__ centers_out) // [C]
{
    const int c = blockIdx.x;
    const int t = threadIdx.x;

    __shared__ float s_d[NNB];
    __shared__ float s_inv[NNB];
    __shared__ float s_embi[NFEAT];
    __shared__ float s_embj[NNB * NFEAT]; // neighbor embeddings pre-scaled by 1/d
    __shared__ float s_norm[NNB * NNB];   // d_jk_norm, indexed q = j*16+k
    __shared__ float s_x[NNB], s_y[NNB], s_z[NNB];
    __shared__ int   s_tj[NNB];
    // double-buffered CTA-wide slab: 2 x 31680 B
    __shared__ __align__(16) float s_stage[2][SLAB_FLOATS];

    // ---- Phase A+B fused: register-chained gathers, one sync ----
    if (t < NNB) {
        float d = dist[c * NNB + t];
        int   a = j_idx[c * NNB + t];
        s_d[t]   = d;
        s_inv[t] = 1.0f / d;
        s_x[t]  = atoms_xyz[a * 3 + 0];
        s_y[t]  = atoms_xyz[a * 3 + 1];
        s_z[t]  = atoms_xyz[a * 3 + 2];
        s_tj[t] = types[a];
    } else if (t >= 32 && t < 64) {
        int lane = t - 32;
        int ai = i_idx[c];            // broadcast
        int ti = types[ai];           // broadcast
        s_embi[lane] = embed[ti * NFEAT + lane];
        if (lane == 0) centers_out[c] = (float)ai;
    }
    __syncthreads();

    // ---- Phase C: scaled neighbor-embedding table + d_jk_norm table ----
    for (int idx = t; idx < NNB * NFEAT; idx += 256) {
        int nb = idx >> 5;
        int f  = idx & 31;
        s_embj[idx] = embed[s_tj[nb] * NFEAT + f] * s_inv[nb];
    }
    {
        int j = t >> 4, k = t & 15;
        float dx = s_x[j] - s_x[k];
        float dy = s_y[j] - s_y[k];
        float dz = s_z[j] - s_z[k];
        float djk = sqrtf(dx * dx + dy * dy + dz * dz);
        float dj = s_d[j], dk = s_d[k];
        float mx = fmaxf(dj, dk), mn = fminf(dj, dk);
        s_norm[t] = (djk - mx + mn) / (2.0f * mn);
    }
    __syncthreads();

    // ---- Phase D: build 80-pair slabs in SMEM, drain each via ONE 31.7KB
    // cp.async.bulk with L2 evict_first (write-once stream: start writebacks
    // early, keep LTS working set shallow) ----
    const int warp = t >> 5;
    const int lane = t & 31;
    const int rot  = (lane - 3) & 31;

    const float embi_a = s_embi[rot];
    const float embi_b = s_embi[(29 + lane) < NFEAT ? (29 + lane) : 0];
    const bool  l0 = (lane == 0), l1 = (lane == 1), l2 = (lane == 2);
    const bool  llt3 = (lane < 3);

    char* gbase = (char*)(out + (size_t)c * PER_C);

    uint64_t policy;
    asm volatile("createpolicy.fractional.L2::evict_first.b64 %0, 1.0;"
                 : "=l"(policy));

    for (int s = 0; s < NSLABS; ++s) {
        float* buf = s_stage[s & 1];

        #pragma unroll
        for (int r = 0; r < PPW; ++r) {
            const int rp = warp * PPW + r;       // row within slab
            const int p  = s * SLAB_PAIRS + rp;  // global pair index
            const int q  = p + (p >> 4) + 1;     // flat n*n index skipping diag
            const int j  = q >> 4;
            const int k  = q & 15;

            const float dj  = s_d[j];
            const float dk  = s_d[k];
            const float njk = s_norm[q];
            const float ejv = s_embj[j * NFEAT + rot];
            const float ekv = s_embj[k * NFEAT + rot];

            float v0 = embi_a;               // [dj, dk, njk, emb_i[0..28]]
            if (l2) v0 = njk;
            if (l1) v0 = dk;
            if (l0) v0 = dj;
            float v1 = llt3 ? embi_b : ejv;  // [emb_i[29..31], e_j[0..28]]
            float v2 = llt3 ? ejv    : ekv;  // [e_j[29..31],  e_k[0..28]]

            float* rb = buf + rp * ROW;
            rb[lane]      = v0;
            rb[32 + lane] = v1;
            rb[64 + lane] = v2;
            if (llt3) rb[96 + lane] = ekv;   // e_k[29..31]
        }

        __syncthreads();   // all warps finished building this slab
        if (t == 0) {
            asm volatile("fence.proxy.async.shared::cta;" ::: "memory");
            uint32_t saddr = (uint32_t)__cvta_generic_to_shared(buf);
            asm volatile(
                "cp.async.bulk.global.shared::cta.bulk_group.L2::cache_hint"
                " [%0], [%1], %2, %3;"
                :: "l"(gbase + (size_t)s * SLAB_BYTES), "r"(saddr),
                   "n"(SLAB_BYTES), "l"(policy)
                : "memory");
            asm volatile("cp.async.bulk.commit_group;" ::: "memory");
            // allow 2 slabs in flight; buffer reused by slab s+1 is the one
            // committed at s-1, which this guarantees has drained
            asm volatile("cp.async.bulk.wait_group 1;" ::: "memory");
        }
        __syncthreads();   // release builders for next slab
    }
    if (t == 0)
        asm volatile("cp.async.bulk.wait_group 0;" ::: "memory");
}

extern "C" void kernel_launch(void* const* d_in, const int* in_sizes, int n_in,
                              void* d_out, int out_size)
{
    const float* atoms_xyz = (const float*)d_in[0];
    const float* embed     = (const float*)d_in[1];
    const float* dist      = (const float*)d_in[2];
    const int*   types     = (const int*)  d_in[3];
    const int*   i_idx     = (const int*)  d_in[4];
    const int*   j_idx     = (const int*)  d_in[5];

    const int C = in_sizes[4];                 // number of centers
    float* out = (float*)d_out;
    float* centers_out = out + (size_t)C * PER_C;

    ang_desc_kernel<<<C, 256>>>(atoms_xyz, embed, dist, types,
                                i_idx, j_idx, out, centers_out);
}